// round 6
// baseline (speedup 1.0000x reference)
#include <cuda_runtime.h>
#include <cuda_bf16.h>
#include <math.h>
#include <stdint.h>

#define B_   2
#define CIN  64
#define H_   80
#define W_   80
#define HW   6400

typedef unsigned long long ull;

// ---------------- f32x2 packed-FMA helpers ----------------
__device__ __forceinline__ void fma2(ull& acc, ull a, ull b){
  asm("fma.rn.f32x2 %0, %1, %2, %0;" : "+l"(acc) : "l"(a), "l"(b));
}
__device__ __forceinline__ ull pack2(float lo, float hi){
  ull r;
  asm("mov.b64 %0, {%1, %2};" : "=l"(r) : "f"(lo), "f"(hi));
  return r;
}
__device__ __forceinline__ float2 unpack2(ull v){
  float lo, hi;
  asm("mov.b64 {%0, %1}, %2;" : "=f"(lo), "=f"(hi) : "l"(v));
  return make_float2(lo, hi);
}

// ---------------- mma.sync m16n8k16 bf16 (sm_80+ baseline, fallback HMMA) ----------------
__device__ __forceinline__ void mma16816(float* c, uint32_t a0, uint32_t a1, uint32_t a2, uint32_t a3,
                                         uint32_t b0, uint32_t b1){
  asm volatile("mma.sync.aligned.m16n8k16.row.col.f32.bf16.bf16.f32 "
    "{%0,%1,%2,%3}, {%4,%5,%6,%7}, {%8,%9}, {%0,%1,%2,%3};"
    : "+f"(c[0]), "+f"(c[1]), "+f"(c[2]), "+f"(c[3])
    : "r"(a0), "r"(a1), "r"(a2), "r"(a3), "r"(b0), "r"(b1));
}

// ---------------- scratch ----------------
__device__ __align__(16) float g_xt[B_*HW*CIN];             // fp32 NHWC for dcn gather
__device__ __align__(16) __nv_bfloat16 g_xhi[B_*HW*CIN];    // bf16 hi NHWC
__device__ __align__(16) __nv_bfloat16 g_xlo[B_*HW*CIN];    // bf16 lo NHWC
__device__ float g_y3[B_*27*HW];
__device__ float g_y5[B_*75*HW];
__device__ float g_y7[B_*147*HW];
__device__ float g_b3[32];
__device__ float g_b5[80];
__device__ float g_b7[160];
__device__ float g_wd3[9*64*64];          // w_dcn repacked [tap][oc][c]
__device__ float g_wd5[25*64*64];
__device__ float g_wd7[49*64*64];
// conv weights bf16, [tap][split(hi,lo)][NP][64]
__device__ __align__(16) __nv_bfloat16 g_gw3[9*2*32*64];
__device__ __align__(16) __nv_bfloat16 g_gw5[25*2*80*64];
__device__ __align__(16) __nv_bfloat16 g_gw7[49*2*160*64];

// ---------------- NCHW -> NHWC transpose (+ bf16 hi/lo split) ----------------
__global__ void transpose_kernel(const float* __restrict__ x, float* __restrict__ xt,
                                 __nv_bfloat16* __restrict__ xhi, __nv_bfloat16* __restrict__ xlo){
  __shared__ float s[64][33];
  int b   = blockIdx.x / 200;
  int hw0 = (blockIdx.x % 200) * 32;
  int tx = threadIdx.x & 31, ty = threadIdx.x >> 5;
  #pragma unroll
  for (int i = 0; i < 8; i++){
    int c = i*8 + ty;
    s[c][tx] = x[((size_t)(b*CIN + c))*HW + hw0 + tx];
  }
  __syncthreads();
  #pragma unroll
  for (int i = 0; i < 8; i++){
    int idx = i*256 + threadIdx.x;
    int hw = idx >> 6, c = idx & 63;
    float v = s[c][hw];
    size_t o = ((size_t)b*HW + hw0 + hw)*CIN + c;
    xt[o] = v;
    __nv_bfloat16 hi = __float2bfloat16(v);
    xhi[o] = hi;
    xlo[o] = __float2bfloat16(v - __bfloat162float(hi));
  }
}

// ---------------- weight packing ----------------
__global__ void pack_kernel(const float* __restrict__ woff, const float* __restrict__ boff,
                            const float* __restrict__ wmask, const float* __restrict__ bmask,
                            const float* __restrict__ wdcn,
                            __nv_bfloat16* __restrict__ gw, float* __restrict__ bp,
                            float* __restrict__ wdp, int KK, int NP){
  int CK = CIN*KK;
  int stride = gridDim.x * blockDim.x;
  int t0 = blockIdx.x*blockDim.x + threadIdx.x;
  // gw[tap][split][n][64]
  for (int i = t0; i < KK*2*NP*64; i += stride){
    int tap = i / (2*NP*64);
    int s   = (i / (NP*64)) & 1;
    int n   = (i / 64) % NP;
    int c   = i & 63;
    float v = 0.f;
    if (n < 2*KK)      v = woff[((size_t)n*CIN + c)*KK + tap];
    else if (n < 3*KK) v = wmask[((size_t)(n-2*KK)*CIN + c)*KK + tap];
    __nv_bfloat16 hi = __float2bfloat16(v);
    gw[i] = (s == 0) ? hi : __float2bfloat16(v - __bfloat162float(hi));
  }
  for (int i = t0; i < NP; i += stride){
    float v = 0.f;
    if (i < 2*KK)      v = boff[i];
    else if (i < 3*KK) v = bmask[i-2*KK];
    bp[i] = v;
  }
  for (int i = t0; i < 64*CK; i += stride){
    int o = i / CK;
    int c = (i % CK) / KK;
    int j = i % KK;
    wdp[((size_t)j*64 + o)*64 + c] = wdcn[i];
  }
}

// ---------------- HMMA implicit-GEMM conv (offset+mask, bf16 3-split) ----------------
// CTA = 8x16 pixel tile, 8 warps (warp = one tile row of 16 px), NF = NP/8 n-frags.
// smem: xs[2][HR*WR][144B-pitch rows of 64 bf16], Bs[2][NP][144B pitch]
template<int K, int NP>
__global__ void conv_mma(const __nv_bfloat16* __restrict__ xhi, const __nv_bfloat16* __restrict__ xlo,
                         const __nv_bfloat16* __restrict__ gw, const float* __restrict__ bp,
                         float* __restrict__ y){
  constexpr int KK = K*K, PAD = K/2, Cout = 3*KK, NF = NP/8;
  constexpr int HR = 8 + K - 1, WR = 16 + K - 1;
  constexpr int PITCH = 144;                  // bytes per 64-bf16 row (conflict-free frags)
  constexpr int XS_SPLIT = HR*WR*PITCH;       // bytes per split
  constexpr int BS_OFF   = 2*XS_SPLIT;
  constexpr int BS_SPLIT = NP*PITCH;

  extern __shared__ __align__(16) char smem[];
  char* xs = smem;
  char* Bs = smem + BS_OFF;

  const int tid  = threadIdx.x;
  const int warp = tid >> 5;
  const int lane = tid & 31;
  const int blk = blockIdx.x;
  const int b = blk / 50;
  const int t = blk % 50;
  const int ty0 = (t / 5) * 8;
  const int tx0 = (t % 5) * 16;

  // ---- stage x halo tile (hi + lo) ----
  for (int i = tid; i < HR*WR*8; i += 256){
    int hp = i >> 3, c16 = i & 7;
    int gy = ty0 - PAD + hp / WR;
    int gx = tx0 - PAD + hp % WR;
    uint4 vh = make_uint4(0,0,0,0), vl = make_uint4(0,0,0,0);
    if (gy >= 0 && gy < H_ && gx >= 0 && gx < W_){
      size_t idx = ((size_t)(b*HW + gy*W_ + gx))*64 + c16*8;
      vh = *(const uint4*)(xhi + idx);
      vl = *(const uint4*)(xlo + idx);
    }
    *(uint4*)(xs + hp*PITCH + c16*16) = vh;
    *(uint4*)(xs + XS_SPLIT + hp*PITCH + c16*16) = vl;
  }

  float acc[NF][4];
  #pragma unroll
  for (int nf = 0; nf < NF; nf++){
    acc[nf][0] = acc[nf][1] = acc[nf][2] = acc[nf][3] = 0.f;
  }

  const int q  = lane & 3;     // k-quad
  const int r8 = lane >> 2;    // row-in-8

  for (int tap = 0; tap < KK; tap++){
    // ---- stage B for this tap (hi + lo) ----
    for (int i = tid; i < 2*NP*8; i += 256){
      int s = i / (NP*8);
      int n = (i >> 3) % NP;
      int c16 = i & 7;
      uint4 v = *(const uint4*)(gw + (((size_t)tap*2 + s)*NP + n)*64 + c16*8);
      *(uint4*)(Bs + s*BS_SPLIT + n*PITCH + c16*16) = v;
    }
    __syncthreads();

    int iy = tap / K, ix = tap % K;
    // A fragment base: pixel (warp+iy, pc+ix) in halo coords; frag row = pc = r8 (+8)
    const char* abase = xs + ((warp + iy)*WR + ix + r8)*PITCH + q*4;

    #pragma unroll
    for (int ks = 0; ks < 4; ks++){
      uint32_t ah0 = *(const uint32_t*)(abase + ks*32);
      uint32_t ah1 = *(const uint32_t*)(abase + 8*PITCH + ks*32);
      uint32_t ah2 = *(const uint32_t*)(abase + ks*32 + 16);
      uint32_t ah3 = *(const uint32_t*)(abase + 8*PITCH + ks*32 + 16);
      uint32_t al0 = *(const uint32_t*)(abase + XS_SPLIT + ks*32);
      uint32_t al1 = *(const uint32_t*)(abase + XS_SPLIT + 8*PITCH + ks*32);
      uint32_t al2 = *(const uint32_t*)(abase + XS_SPLIT + ks*32 + 16);
      uint32_t al3 = *(const uint32_t*)(abase + XS_SPLIT + 8*PITCH + ks*32 + 16);
      #pragma unroll
      for (int nf = 0; nf < NF; nf++){
        const char* bbase = Bs + (nf*8 + r8)*PITCH + q*4 + ks*32;
        uint32_t bh0 = *(const uint32_t*)(bbase);
        uint32_t bh1 = *(const uint32_t*)(bbase + 16);
        uint32_t bl0 = *(const uint32_t*)(bbase + BS_SPLIT);
        uint32_t bl1 = *(const uint32_t*)(bbase + BS_SPLIT + 16);
        mma16816(acc[nf], ah0, ah1, ah2, ah3, bh0, bh1);
        mma16816(acc[nf], ah0, ah1, ah2, ah3, bl0, bl1);
        mma16816(acc[nf], al0, al1, al2, al3, bh0, bh1);
      }
    }
    __syncthreads();
  }

  // ---- epilogue: C frag -> y (NCHW), bias + sigmoid on mask channels ----
  const int h = ty0 + warp;
  const int col0 = (lane & 3)*2;
  #pragma unroll
  for (int nf = 0; nf < NF; nf++){
    #pragma unroll
    for (int e = 0; e < 4; e++){
      int oc = nf*8 + col0 + (e & 1);
      int pc = r8 + (e >> 1)*8;
      if (oc < Cout){
        float v = acc[nf][e] + __ldg(bp + oc);
        if (oc >= 2*KK) v = 1.f/(1.f + __expf(-v));
        y[((size_t)(b*Cout + oc))*HW + h*W_ + tx0 + pc] = v;
      }
    }
  }
}

// ---------------- fused deformable sampling + DCN contraction (FFMA2) ----------------
template<int K>
__global__ void dcn_kernel(const float* __restrict__ xt, const float* __restrict__ offm,
                           const float* __restrict__ wdp, float* __restrict__ out,
                           int outBase){
  constexpr int KK = K*K, PAD = K/2, C3 = 3*KK;
  __shared__ __align__(16) float wsT[16][260];
  __shared__ __align__(16) float samp[32][68];
  const int tid  = threadIdx.x;
  const int b    = blockIdx.y;
  const int p0   = blockIdx.x * 32;
  const int o0   = tid & 15;
  const int pg   = tid >> 4;
  const int wid  = tid >> 5;
  const int lane = tid & 31;
  const float* xb   = xt + (size_t)b*HW*CIN;
  const float* offb = offm + (size_t)b*C3*HW;

  ull p00, p01, p10, p11, p20, p21, p30, p31;
  p00=p01=p10=p11=p20=p21=p30=p31 = pack2(0.f, 0.f);

  for (int j = 0; j < KK; j++){
    const float4* wsrc = (const float4*)(wdp + (size_t)j*4096);
    #pragma unroll
    for (int i = tid; i < 1024; i += 256){
      float4 v = __ldg(wsrc + i);
      *(float4*)&wsT[i & 15][(i >> 4)*4] = v;
    }
    int iy = j / K, ix = j - iy*K;
    #pragma unroll
    for (int r = 0; r < 4; r++){
      int p = wid*4 + r;
      int pix = p0 + p;
      int h = pix / W_, w = pix - h*W_;
      float oy = __ldg(offb + (size_t)(2*j)*HW + pix);
      float ox = __ldg(offb + (size_t)(2*j + 1)*HW + pix);
      float m  = __ldg(offb + (size_t)(2*KK + j)*HW + pix);
      float py = (float)(h - PAD + iy) + oy;
      float px = (float)(w - PAD + ix) + ox;
      float y0f = floorf(py), x0f = floorf(px);
      float wy1 = py - y0f, wx1 = px - x0f;
      float wy0 = 1.f - wy1, wx0 = 1.f - wx1;
      int y0 = (int)y0f, x0 = (int)x0f;
      bool vy0 = (y0 >= 0)  && (y0 < H_);
      bool vy1 = (y0 >= -1) && (y0 < H_ - 1);
      bool vx0 = (x0 >= 0)  && (x0 < W_);
      bool vx1 = (x0 >= -1) && (x0 < W_ - 1);
      float w00 = (vy0 && vx0) ? wy0*wx0*m : 0.f;
      float w01 = (vy0 && vx1) ? wy0*wx1*m : 0.f;
      float w10 = (vy1 && vx0) ? wy1*wx0*m : 0.f;
      float w11 = (vy1 && vx1) ? wy1*wx1*m : 0.f;
      int y0c = min(max(y0, 0), H_-1), y1c = min(max(y0 + 1, 0), H_-1);
      int x0c = min(max(x0, 0), W_-1), x1c = min(max(x0 + 1, 0), W_-1);
      int c = lane * 2;
      float2 t00 = *(const float2*)(xb + (size_t)(y0c*W_ + x0c)*CIN + c);
      float2 t01 = *(const float2*)(xb + (size_t)(y0c*W_ + x1c)*CIN + c);
      float2 t10 = *(const float2*)(xb + (size_t)(y1c*W_ + x0c)*CIN + c);
      float2 t11 = *(const float2*)(xb + (size_t)(y1c*W_ + x1c)*CIN + c);
      float vx = w00*t00.x + w01*t01.x + w10*t10.x + w11*t11.x;
      float vy = w00*t00.y + w01*t01.y + w10*t10.y + w11*t11.y;
      *(float2*)&samp[p][c] = make_float2(vx, vy);
    }
    __syncthreads();
    #pragma unroll
    for (int c4 = 0; c4 < 16; c4++){
      ulonglong2 w0 = *(const ulonglong2*)&wsT[c4][(o0      )*4];
      ulonglong2 w1 = *(const ulonglong2*)&wsT[c4][(o0 + 16 )*4];
      ulonglong2 w2 = *(const ulonglong2*)&wsT[c4][(o0 + 32 )*4];
      ulonglong2 w3 = *(const ulonglong2*)&wsT[c4][(o0 + 48 )*4];
      ulonglong2 s0 = *(const ulonglong2*)&samp[pg*2    ][c4*4];
      ulonglong2 s1 = *(const ulonglong2*)&samp[pg*2 + 1][c4*4];
      fma2(p00, w0.x, s0.x); fma2(p00, w0.y, s0.y);
      fma2(p01, w0.x, s1.x); fma2(p01, w0.y, s1.y);
      fma2(p10, w1.x, s0.x); fma2(p10, w1.y, s0.y);
      fma2(p11, w1.x, s1.x); fma2(p11, w1.y, s1.y);
      fma2(p20, w2.x, s0.x); fma2(p20, w2.y, s0.y);
      fma2(p21, w2.x, s1.x); fma2(p21, w2.y, s1.y);
      fma2(p30, w3.x, s0.x); fma2(p30, w3.y, s0.y);
      fma2(p31, w3.x, s1.x); fma2(p31, w3.y, s1.y);
    }
    __syncthreads();
  }

  float2 u;
  float a00, a01, a10, a11, a20, a21, a30, a31;
  u = unpack2(p00); a00 = u.x + u.y;
  u = unpack2(p01); a01 = u.x + u.y;
  u = unpack2(p10); a10 = u.x + u.y;
  u = unpack2(p11); a11 = u.x + u.y;
  u = unpack2(p20); a20 = u.x + u.y;
  u = unpack2(p21); a21 = u.x + u.y;
  u = unpack2(p30); a30 = u.x + u.y;
  u = unpack2(p31); a31 = u.x + u.y;

  int pxb = p0 + pg*2;
  size_t base = ((size_t)b*192 + outBase)*HW;
  *(float2*)&out[base + (size_t)(o0      )*HW + pxb] = make_float2(a00, a01);
  *(float2*)&out[base + (size_t)(o0 + 16 )*HW + pxb] = make_float2(a10, a11);
  *(float2*)&out[base + (size_t)(o0 + 32 )*HW + pxb] = make_float2(a20, a21);
  *(float2*)&out[base + (size_t)(o0 + 48 )*HW + pxb] = make_float2(a30, a31);
}

// ---------------- launch ----------------
extern "C" void kernel_launch(void* const* d_in, const int* in_sizes, int n_in,
                              void* d_out, int out_size){
  const float* x       = (const float*)d_in[0];
  const float* w_off3  = (const float*)d_in[1];
  const float* b_off3  = (const float*)d_in[2];
  const float* w_mask3 = (const float*)d_in[3];
  const float* b_mask3 = (const float*)d_in[4];
  const float* w_dcn3  = (const float*)d_in[5];
  const float* w_off5  = (const float*)d_in[6];
  const float* b_off5  = (const float*)d_in[7];
  const float* w_mask5 = (const float*)d_in[8];
  const float* b_mask5 = (const float*)d_in[9];
  const float* w_dcn5  = (const float*)d_in[10];
  const float* w_off7  = (const float*)d_in[11];
  const float* b_off7  = (const float*)d_in[12];
  const float* w_mask7 = (const float*)d_in[13];
  const float* b_mask7 = (const float*)d_in[14];
  const float* w_dcn7  = (const float*)d_in[15];
  float* out = (float*)d_out;

  float *xt, *y3, *y5, *y7, *b3, *b5, *b7, *wd3, *wd5, *wd7;
  __nv_bfloat16 *xhi, *xlo, *gw3, *gw5, *gw7;
  cudaGetSymbolAddress((void**)&xt,  g_xt);
  cudaGetSymbolAddress((void**)&xhi, g_xhi);
  cudaGetSymbolAddress((void**)&xlo, g_xlo);
  cudaGetSymbolAddress((void**)&y3,  g_y3);
  cudaGetSymbolAddress((void**)&y5,  g_y5);
  cudaGetSymbolAddress((void**)&y7,  g_y7);
  cudaGetSymbolAddress((void**)&b3,  g_b3);
  cudaGetSymbolAddress((void**)&b5,  g_b5);
  cudaGetSymbolAddress((void**)&b7,  g_b7);
  cudaGetSymbolAddress((void**)&wd3, g_wd3);
  cudaGetSymbolAddress((void**)&wd5, g_wd5);
  cudaGetSymbolAddress((void**)&wd7, g_wd7);
  cudaGetSymbolAddress((void**)&gw3, g_gw3);
  cudaGetSymbolAddress((void**)&gw5, g_gw5);
  cudaGetSymbolAddress((void**)&gw7, g_gw7);

  // smem sizes: 2*HR*WR*144 + 2*NP*144
  const int smem3 = 2*10*18*144 + 2*32*144;    //  61056
  const int smem5 = 2*12*20*144 + 2*80*144;    //  92160
  const int smem7 = 2*14*22*144 + 2*160*144;   // 134784
  cudaFuncSetAttribute(conv_mma<3,32>,  cudaFuncAttributeMaxDynamicSharedMemorySize, smem3);
  cudaFuncSetAttribute(conv_mma<5,80>,  cudaFuncAttributeMaxDynamicSharedMemorySize, smem5);
  cudaFuncSetAttribute(conv_mma<7,160>, cudaFuncAttributeMaxDynamicSharedMemorySize, smem7);

  transpose_kernel<<<400, 256>>>(x, xt, xhi, xlo);
  pack_kernel<<<256, 256>>>(w_off3, b_off3, w_mask3, b_mask3, w_dcn3, gw3, b3, wd3, 9, 32);
  pack_kernel<<<256, 256>>>(w_off5, b_off5, w_mask5, b_mask5, w_dcn5, gw5, b5, wd5, 25, 80);
  pack_kernel<<<256, 256>>>(w_off7, b_off7, w_mask7, b_mask7, w_dcn7, gw7, b7, wd7, 49, 160);

  conv_mma<3,32> <<<100, 256, smem3>>>(xhi, xlo, gw3, b3, y3);
  conv_mma<5,80> <<<100, 256, smem5>>>(xhi, xlo, gw5, b5, y5);
  conv_mma<7,160><<<100, 256, smem7>>>(xhi, xlo, gw7, b7, y7);

  dcn_kernel<3><<<dim3(200, B_), 256>>>(xt, y3, wd3, out, 0);
  dcn_kernel<5><<<dim3(200, B_), 256>>>(xt, y5, wd5, out, 64);
  dcn_kernel<7><<<dim3(200, B_), 256>>>(xt, y7, wd7, out, 128);
}

// round 7
// speedup vs baseline: 1.7428x; 1.7428x over previous
#include <cuda_runtime.h>
#include <cuda_bf16.h>
#include <math.h>
#include <stdint.h>

#define B_   2
#define CIN  64
#define H_   80
#define W_   80
#define HW   6400

// ---------------- mma.sync m16n8k16 bf16 (sm_80+ baseline) ----------------
__device__ __forceinline__ void mma16816(float* c, uint32_t a0, uint32_t a1, uint32_t a2, uint32_t a3,
                                         uint32_t b0, uint32_t b1){
  asm volatile("mma.sync.aligned.m16n8k16.row.col.f32.bf16.bf16.f32 "
    "{%0,%1,%2,%3}, {%4,%5,%6,%7}, {%8,%9}, {%0,%1,%2,%3};"
    : "+f"(c[0]), "+f"(c[1]), "+f"(c[2]), "+f"(c[3])
    : "r"(a0), "r"(a1), "r"(a2), "r"(a3), "r"(b0), "r"(b1));
}

// ---------------- scratch ----------------
__device__ __align__(16) float g_xt[B_*HW*CIN];             // fp32 NHWC for dcn gather
__device__ __align__(16) __nv_bfloat16 g_xhi[B_*HW*CIN];
__device__ __align__(16) __nv_bfloat16 g_xlo[B_*HW*CIN];
__device__ float g_y3[B_*27*HW];
__device__ float g_y5[B_*75*HW];
__device__ float g_y7[B_*147*HW];
__device__ float g_b3[32];
__device__ float g_b5[80];
__device__ float g_b7[160];
// conv weights bf16, [tap][split(hi,lo)][NP][64]
__device__ __align__(16) __nv_bfloat16 g_gw3[9*2*32*64];
__device__ __align__(16) __nv_bfloat16 g_gw5[25*2*80*64];
__device__ __align__(16) __nv_bfloat16 g_gw7[49*2*160*64];
// dcn weights bf16, [tap][split(hi,lo)][64 oc][64 c]
__device__ __align__(16) __nv_bfloat16 g_wdb3[9*2*64*64];
__device__ __align__(16) __nv_bfloat16 g_wdb5[25*2*64*64];
__device__ __align__(16) __nv_bfloat16 g_wdb7[49*2*64*64];

// ---------------- NCHW -> NHWC transpose (+ bf16 hi/lo split) ----------------
__global__ void transpose_kernel(const float* __restrict__ x, float* __restrict__ xt,
                                 __nv_bfloat16* __restrict__ xhi, __nv_bfloat16* __restrict__ xlo){
  __shared__ float s[64][33];
  int b   = blockIdx.x / 200;
  int hw0 = (blockIdx.x % 200) * 32;
  int tx = threadIdx.x & 31, ty = threadIdx.x >> 5;
  #pragma unroll
  for (int i = 0; i < 8; i++){
    int c = i*8 + ty;
    s[c][tx] = x[((size_t)(b*CIN + c))*HW + hw0 + tx];
  }
  __syncthreads();
  #pragma unroll
  for (int i = 0; i < 8; i++){
    int idx = i*256 + threadIdx.x;
    int hw = idx >> 6, c = idx & 63;
    float v = s[c][hw];
    size_t o = ((size_t)b*HW + hw0 + hw)*CIN + c;
    xt[o] = v;
    __nv_bfloat16 hi = __float2bfloat16(v);
    xhi[o] = hi;
    xlo[o] = __float2bfloat16(v - __bfloat162float(hi));
  }
}

// ---------------- weight packing ----------------
__global__ void pack_kernel(const float* __restrict__ woff, const float* __restrict__ boff,
                            const float* __restrict__ wmask, const float* __restrict__ bmask,
                            const float* __restrict__ wdcn,
                            __nv_bfloat16* __restrict__ gw, float* __restrict__ bp,
                            __nv_bfloat16* __restrict__ wdb, int KK, int NP){
  int stride = gridDim.x * blockDim.x;
  int t0 = blockIdx.x*blockDim.x + threadIdx.x;
  // gw[tap][split][n][64]
  for (int i = t0; i < KK*2*NP*64; i += stride){
    int tap = i / (2*NP*64);
    int s   = (i / (NP*64)) & 1;
    int n   = (i / 64) % NP;
    int c   = i & 63;
    float v = 0.f;
    if (n < 2*KK)      v = woff[((size_t)n*CIN + c)*KK + tap];
    else if (n < 3*KK) v = wmask[((size_t)(n-2*KK)*CIN + c)*KK + tap];
    __nv_bfloat16 hi = __float2bfloat16(v);
    gw[i] = (s == 0) ? hi : __float2bfloat16(v - __bfloat162float(hi));
  }
  for (int i = t0; i < NP; i += stride){
    float v = 0.f;
    if (i < 2*KK)      v = boff[i];
    else if (i < 3*KK) v = bmask[i-2*KK];
    bp[i] = v;
  }
  // wdb[tap][split][oc][c]
  for (int i = t0; i < KK*2*64*64; i += stride){
    int tap = i / (2*4096);
    int s   = (i / 4096) & 1;
    int n   = (i / 64) % 64;
    int c   = i & 63;
    float v = wdcn[((size_t)n*64 + c)*KK + tap];
    __nv_bfloat16 hi = __float2bfloat16(v);
    wdb[i] = (s == 0) ? hi : __float2bfloat16(v - __bfloat162float(hi));
  }
}

// ---------------- HMMA implicit-GEMM conv branch (device fn) ----------------
template<int K, int NP>
__device__ __forceinline__ void conv_branch(char* smem,
                         const __nv_bfloat16* __restrict__ xhi, const __nv_bfloat16* __restrict__ xlo,
                         const __nv_bfloat16* __restrict__ gw, const float* __restrict__ bp,
                         float* __restrict__ y, int blk){
  constexpr int KK = K*K, PAD = K/2, Cout = 3*KK, NF = NP/8;
  constexpr int HR = 8 + K - 1, WR = 16 + K - 1;
  constexpr int PITCH = 144;
  constexpr int XS_SPLIT = HR*WR*PITCH;
  constexpr int BS_OFF   = 2*XS_SPLIT;
  constexpr int BS_SPLIT = NP*PITCH;

  char* xs = smem;
  char* Bs = smem + BS_OFF;

  const int tid  = threadIdx.x;
  const int warp = tid >> 5;
  const int lane = tid & 31;
  const int b = blk / 50;
  const int t = blk % 50;
  const int ty0 = (t / 5) * 8;
  const int tx0 = (t % 5) * 16;

  for (int i = tid; i < HR*WR*8; i += 256){
    int hp = i >> 3, c16 = i & 7;
    int gy = ty0 - PAD + hp / WR;
    int gx = tx0 - PAD + hp % WR;
    uint4 vh = make_uint4(0,0,0,0), vl = make_uint4(0,0,0,0);
    if (gy >= 0 && gy < H_ && gx >= 0 && gx < W_){
      size_t idx = ((size_t)(b*HW + gy*W_ + gx))*64 + c16*8;
      vh = *(const uint4*)(xhi + idx);
      vl = *(const uint4*)(xlo + idx);
    }
    *(uint4*)(xs + hp*PITCH + c16*16) = vh;
    *(uint4*)(xs + XS_SPLIT + hp*PITCH + c16*16) = vl;
  }

  float acc[NF][4];
  #pragma unroll
  for (int nf = 0; nf < NF; nf++){
    acc[nf][0] = acc[nf][1] = acc[nf][2] = acc[nf][3] = 0.f;
  }

  const int q  = lane & 3;
  const int r8 = lane >> 2;

  for (int tap = 0; tap < KK; tap++){
    for (int i = tid; i < 2*NP*8; i += 256){
      int s = i / (NP*8);
      int n = (i >> 3) % NP;
      int c16 = i & 7;
      uint4 v = *(const uint4*)(gw + (((size_t)tap*2 + s)*NP + n)*64 + c16*8);
      *(uint4*)(Bs + s*BS_SPLIT + n*PITCH + c16*16) = v;
    }
    __syncthreads();

    int iy = tap / K, ix = tap % K;
    const char* abase = xs + ((warp + iy)*WR + ix + r8)*PITCH + q*4;

    #pragma unroll
    for (int ks = 0; ks < 4; ks++){
      uint32_t ah0 = *(const uint32_t*)(abase + ks*32);
      uint32_t ah1 = *(const uint32_t*)(abase + 8*PITCH + ks*32);
      uint32_t ah2 = *(const uint32_t*)(abase + ks*32 + 16);
      uint32_t ah3 = *(const uint32_t*)(abase + 8*PITCH + ks*32 + 16);
      uint32_t al0 = *(const uint32_t*)(abase + XS_SPLIT + ks*32);
      uint32_t al1 = *(const uint32_t*)(abase + XS_SPLIT + 8*PITCH + ks*32);
      uint32_t al2 = *(const uint32_t*)(abase + XS_SPLIT + ks*32 + 16);
      uint32_t al3 = *(const uint32_t*)(abase + XS_SPLIT + 8*PITCH + ks*32 + 16);
      #pragma unroll
      for (int nf = 0; nf < NF; nf++){
        const char* bbase = Bs + (nf*8 + r8)*PITCH + q*4 + ks*32;
        uint32_t bh0 = *(const uint32_t*)(bbase);
        uint32_t bh1 = *(const uint32_t*)(bbase + 16);
        uint32_t bl0 = *(const uint32_t*)(bbase + BS_SPLIT);
        uint32_t bl1 = *(const uint32_t*)(bbase + BS_SPLIT + 16);
        mma16816(acc[nf], ah0, ah1, ah2, ah3, bh0, bh1);
        mma16816(acc[nf], ah0, ah1, ah2, ah3, bl0, bl1);
        mma16816(acc[nf], al0, al1, al2, al3, bh0, bh1);
      }
    }
    __syncthreads();
  }

  const int h = ty0 + warp;
  const int col0 = (lane & 3)*2;
  #pragma unroll
  for (int nf = 0; nf < NF; nf++){
    #pragma unroll
    for (int e = 0; e < 4; e++){
      int oc = nf*8 + col0 + (e & 1);
      int pc = r8 + (e >> 1)*8;
      if (oc < Cout){
        float v = acc[nf][e] + __ldg(bp + oc);
        if (oc >= 2*KK) v = 1.f/(1.f + __expf(-v));
        y[((size_t)(b*Cout + oc))*HW + h*W_ + tx0 + pc] = v;
      }
    }
  }
}

// merged conv: 300 blocks, heavy branch first
__global__ void conv_all(const __nv_bfloat16* __restrict__ xhi, const __nv_bfloat16* __restrict__ xlo,
                         const __nv_bfloat16* __restrict__ gw3, const __nv_bfloat16* __restrict__ gw5,
                         const __nv_bfloat16* __restrict__ gw7,
                         const float* __restrict__ b3, const float* __restrict__ b5, const float* __restrict__ b7,
                         float* __restrict__ y3, float* __restrict__ y5, float* __restrict__ y7){
  extern __shared__ __align__(16) char smem[];
  int blk = blockIdx.x;
  if (blk < 100)       conv_branch<7,160>(smem, xhi, xlo, gw7, b7, y7, blk);
  else if (blk < 200)  conv_branch<5,80> (smem, xhi, xlo, gw5, b5, y5, blk - 100);
  else                 conv_branch<3,32> (smem, xhi, xlo, gw3, b3, y3, blk - 200);
}

// ---------------- HMMA deformable sampling + DCN contraction ----------------
// CTA = 32 pixels. Per tap: gather -> bf16 hi/lo samp[32][64], stage W hi/lo, 3-split mma.
// smem: sampH(4608) sampL(4608) Bs(2*9216)
template<int K>
__device__ __forceinline__ void dcn_branch(char* smem,
                          const float* __restrict__ xt, const float* __restrict__ offm,
                          const __nv_bfloat16* __restrict__ wdb, float* __restrict__ out,
                          int outBase, int blk){
  constexpr int KK = K*K, PAD = K/2, C3 = 3*KK;
  constexpr int PITCH = 144;
  char* sampH = smem;
  char* sampL = smem + 4608;
  char* Bs    = smem + 9216;
  constexpr int BS_SPLIT = 64*PITCH;  // 9216

  const int tid  = threadIdx.x;
  const int warp = tid >> 5;
  const int lane = tid & 31;
  const int q  = lane & 3;
  const int r8 = lane >> 2;
  const int b  = blk / 200;
  const int p0 = (blk % 200) * 32;
  const int mf = warp & 1;          // m-frag (pixels mf*16..)
  const int nf0 = warp >> 1;        // n-frags nf0, nf0+4
  const float* xb   = xt + (size_t)b*HW*CIN;
  const float* offb = offm + (size_t)b*C3*HW;

  float acc[2][4];
  acc[0][0]=acc[0][1]=acc[0][2]=acc[0][3]=0.f;
  acc[1][0]=acc[1][1]=acc[1][2]=acc[1][3]=0.f;

  for (int j = 0; j < KK; j++){
    // stage dcn weights hi/lo for this tap
    for (int i = tid; i < 1024; i += 256){
      int s = i >> 9;
      int n = (i >> 3) & 63;
      int c16 = i & 7;
      uint4 v = *(const uint4*)(wdb + (((size_t)j*2 + s)*64 + n)*64 + c16*8);
      *(uint4*)(Bs + s*BS_SPLIT + n*PITCH + c16*16) = v;
    }
    // bilinear gather: warp handles pixels warp*4..+3, lane -> 2 channels
    int iy = j / K, ix = j - iy*K;
    #pragma unroll
    for (int r = 0; r < 4; r++){
      int p = warp*4 + r;
      int pix = p0 + p;
      int h = pix / W_, w = pix - h*W_;
      float oy = __ldg(offb + (size_t)(2*j)*HW + pix);
      float ox = __ldg(offb + (size_t)(2*j + 1)*HW + pix);
      float m  = __ldg(offb + (size_t)(2*KK + j)*HW + pix);
      float py = (float)(h - PAD + iy) + oy;
      float px = (float)(w - PAD + ix) + ox;
      float y0f = floorf(py), x0f = floorf(px);
      float wy1 = py - y0f, wx1 = px - x0f;
      float wy0 = 1.f - wy1, wx0 = 1.f - wx1;
      int y0 = (int)y0f, x0 = (int)x0f;
      bool vy0 = (y0 >= 0)  && (y0 < H_);
      bool vy1 = (y0 >= -1) && (y0 < H_ - 1);
      bool vx0 = (x0 >= 0)  && (x0 < W_);
      bool vx1 = (x0 >= -1) && (x0 < W_ - 1);
      float w00 = (vy0 && vx0) ? wy0*wx0*m : 0.f;
      float w01 = (vy0 && vx1) ? wy0*wx1*m : 0.f;
      float w10 = (vy1 && vx0) ? wy1*wx0*m : 0.f;
      float w11 = (vy1 && vx1) ? wy1*wx1*m : 0.f;
      int y0c = min(max(y0, 0), H_-1), y1c = min(max(y0 + 1, 0), H_-1);
      int x0c = min(max(x0, 0), W_-1), x1c = min(max(x0 + 1, 0), W_-1);
      int c = lane * 2;
      float2 t00 = *(const float2*)(xb + (size_t)(y0c*W_ + x0c)*CIN + c);
      float2 t01 = *(const float2*)(xb + (size_t)(y0c*W_ + x1c)*CIN + c);
      float2 t10 = *(const float2*)(xb + (size_t)(y1c*W_ + x0c)*CIN + c);
      float2 t11 = *(const float2*)(xb + (size_t)(y1c*W_ + x1c)*CIN + c);
      float vx = w00*t00.x + w01*t01.x + w10*t10.x + w11*t11.x;
      float vy = w00*t00.y + w01*t01.y + w10*t10.y + w11*t11.y;
      __nv_bfloat16 hx = __float2bfloat16(vx);
      __nv_bfloat16 hy = __float2bfloat16(vy);
      __nv_bfloat16 lx = __float2bfloat16(vx - __bfloat162float(hx));
      __nv_bfloat16 ly = __float2bfloat16(vy - __bfloat162float(hy));
      __nv_bfloat162 hv; hv.x = hx; hv.y = hy;
      __nv_bfloat162 lv; lv.x = lx; lv.y = ly;
      *(__nv_bfloat162*)(sampH + p*PITCH + lane*4) = hv;
      *(__nv_bfloat162*)(sampL + p*PITCH + lane*4) = lv;
    }
    __syncthreads();
    // 3-split mma: A = samp rows (pixels), B = weights [oc][c]
    const char* abase = sampH + (mf*16 + r8)*PITCH + q*4;
    #pragma unroll
    for (int ks = 0; ks < 4; ks++){
      uint32_t ah0 = *(const uint32_t*)(abase + ks*32);
      uint32_t ah1 = *(const uint32_t*)(abase + 8*PITCH + ks*32);
      uint32_t ah2 = *(const uint32_t*)(abase + ks*32 + 16);
      uint32_t ah3 = *(const uint32_t*)(abase + 8*PITCH + ks*32 + 16);
      uint32_t al0 = *(const uint32_t*)(abase + 4608 + ks*32);
      uint32_t al1 = *(const uint32_t*)(abase + 4608 + 8*PITCH + ks*32);
      uint32_t al2 = *(const uint32_t*)(abase + 4608 + ks*32 + 16);
      uint32_t al3 = *(const uint32_t*)(abase + 4608 + 8*PITCH + ks*32 + 16);
      #pragma unroll
      for (int nfi = 0; nfi < 2; nfi++){
        int nf = nf0 + nfi*4;
        const char* bbase = Bs + (nf*8 + r8)*PITCH + q*4 + ks*32;
        uint32_t bh0 = *(const uint32_t*)(bbase);
        uint32_t bh1 = *(const uint32_t*)(bbase + 16);
        uint32_t bl0 = *(const uint32_t*)(bbase + BS_SPLIT);
        uint32_t bl1 = *(const uint32_t*)(bbase + BS_SPLIT + 16);
        mma16816(acc[nfi], ah0, ah1, ah2, ah3, bh0, bh1);
        mma16816(acc[nfi], ah0, ah1, ah2, ah3, bl0, bl1);
        mma16816(acc[nfi], al0, al1, al2, al3, bh0, bh1);
      }
    }
    __syncthreads();
  }

  // epilogue: C frag -> out[b][outBase+oc][pix]
  size_t base = ((size_t)b*192 + outBase)*HW;
  #pragma unroll
  for (int nfi = 0; nfi < 2; nfi++){
    int nf = nf0 + nfi*4;
    #pragma unroll
    for (int e = 0; e < 4; e++){
      int oc = nf*8 + 2*q + (e & 1);
      int pix = p0 + mf*16 + r8 + (e >> 1)*8;
      out[base + (size_t)oc*HW + pix] = acc[nfi][e];
    }
  }
}

// merged dcn: 1200 blocks, heavy branch first
__global__ void dcn_all(const float* __restrict__ xt,
                        const float* __restrict__ y3, const float* __restrict__ y5, const float* __restrict__ y7,
                        const __nv_bfloat16* __restrict__ wdb3, const __nv_bfloat16* __restrict__ wdb5,
                        const __nv_bfloat16* __restrict__ wdb7,
                        float* __restrict__ out){
  extern __shared__ __align__(16) char smem[];
  int blk = blockIdx.x;
  if (blk < 400)      dcn_branch<7>(smem, xt, y7, wdb7, out, 128, blk);
  else if (blk < 800) dcn_branch<5>(smem, xt, y5, wdb5, out, 64,  blk - 400);
  else                dcn_branch<3>(smem, xt, y3, wdb3, out, 0,   blk - 800);
}

// ---------------- launch ----------------
extern "C" void kernel_launch(void* const* d_in, const int* in_sizes, int n_in,
                              void* d_out, int out_size){
  const float* x       = (const float*)d_in[0];
  const float* w_off3  = (const float*)d_in[1];
  const float* b_off3  = (const float*)d_in[2];
  const float* w_mask3 = (const float*)d_in[3];
  const float* b_mask3 = (const float*)d_in[4];
  const float* w_dcn3  = (const float*)d_in[5];
  const float* w_off5  = (const float*)d_in[6];
  const float* b_off5  = (const float*)d_in[7];
  const float* w_mask5 = (const float*)d_in[8];
  const float* b_mask5 = (const float*)d_in[9];
  const float* w_dcn5  = (const float*)d_in[10];
  const float* w_off7  = (const float*)d_in[11];
  const float* b_off7  = (const float*)d_in[12];
  const float* w_mask7 = (const float*)d_in[13];
  const float* b_mask7 = (const float*)d_in[14];
  const float* w_dcn7  = (const float*)d_in[15];
  float* out = (float*)d_out;

  float *xt, *y3, *y5, *y7, *b3, *b5, *b7;
  __nv_bfloat16 *xhi, *xlo, *gw3, *gw5, *gw7, *wdb3, *wdb5, *wdb7;
  cudaGetSymbolAddress((void**)&xt,  g_xt);
  cudaGetSymbolAddress((void**)&xhi, g_xhi);
  cudaGetSymbolAddress((void**)&xlo, g_xlo);
  cudaGetSymbolAddress((void**)&y3,  g_y3);
  cudaGetSymbolAddress((void**)&y5,  g_y5);
  cudaGetSymbolAddress((void**)&y7,  g_y7);
  cudaGetSymbolAddress((void**)&b3,  g_b3);
  cudaGetSymbolAddress((void**)&b5,  g_b5);
  cudaGetSymbolAddress((void**)&b7,  g_b7);
  cudaGetSymbolAddress((void**)&gw3, g_gw3);
  cudaGetSymbolAddress((void**)&gw5, g_gw5);
  cudaGetSymbolAddress((void**)&gw7, g_gw7);
  cudaGetSymbolAddress((void**)&wdb3, g_wdb3);
  cudaGetSymbolAddress((void**)&wdb5, g_wdb5);
  cudaGetSymbolAddress((void**)&wdb7, g_wdb7);

  const int smemConv = 2*14*22*144 + 2*160*144;   // 134784 (k7 worst case)
  const int smemDcn  = 4608*2 + 2*9216;           // 27648
  cudaFuncSetAttribute(conv_all, cudaFuncAttributeMaxDynamicSharedMemorySize, smemConv);
  cudaFuncSetAttribute(dcn_all,  cudaFuncAttributeMaxDynamicSharedMemorySize, smemDcn);

  transpose_kernel<<<400, 256>>>(x, xt, xhi, xlo);
  pack_kernel<<<256, 256>>>(w_off3, b_off3, w_mask3, b_mask3, w_dcn3, gw3, b3, wdb3, 9, 32);
  pack_kernel<<<256, 256>>>(w_off5, b_off5, w_mask5, b_mask5, w_dcn5, gw5, b5, wdb5, 25, 80);
  pack_kernel<<<256, 256>>>(w_off7, b_off7, w_mask7, b_mask7, w_dcn7, gw7, b7, wdb7, 49, 160);

  conv_all<<<300, 256, smemConv>>>(xhi, xlo, gw3, gw5, gw7, b3, b5, b7, y3, y5, y7);
  dcn_all<<<1200, 256, smemDcn>>>(xt, y3, y5, y7, wdb3, wdb5, wdb7, out);
}